// round 15
// baseline (speedup 1.0000x reference)
#include <cuda_runtime.h>
#include <cuda_fp16.h>
#include <cstdint>

#define BB   8
#define CC   768
#define DD   512
#define HWW  1024
#define LQQ  2048
#define MROWS (BB*LQQ)   // 16384

// ---------------- scratch (device globals) ----------------
__device__ uint4 g_xth [2][8192*768/8];
__device__ uint4 g_w1h [2*512*768/8];                 // conv1 weights v|i
__device__ uint4 g_wvoa[768*512/8];                   // [w_val(512) ; w_oa(256)]
__device__ uint4 g_wouth[512*512/8];
__device__ uint4 g_wch_[768*1024/8];
__device__ uint4 g_preh[MROWS*512/8];                 // conv1 out fp16
__device__ uint4 g_srch[MROWS*512/8];
__device__ uint4 g_msh[MROWS*512/8];
__device__ uint4 g_cath[8192*1024/8];
__device__ uint4 g_vph [MROWS*512/8];                 // vproj fp16
__device__ uint4 g_attnoh[MROWS*512/8];               // attn out fp16
__device__ uint4 g_conv2h[BB*CC*HWW/8];               // conv2 out fp16
__device__ float4 g_oa4   [MROWS*256/4];
__device__ float  g_lep  [512];                       // le@Woa^T + boa, [lvl][256]
__device__ float  g_b1   [1024];                      // conv1 bias v|i
__device__ float  g_stats1[BB*2*32*2];
__device__ float  g_stats2[BB*32*2];

// ---------------- PTX helpers (sm_80-compatible ISA only) ----------------
__device__ __forceinline__ uint32_t smem_u32(const void* p) {
    uint32_t a;
    asm("{ .reg .u64 t; cvta.to.shared.u64 t, %1; cvt.u32.u64 %0, t; }" : "=r"(a) : "l"(p));
    return a;
}
#define CP16(s, g) \
    asm volatile("cp.async.cg.shared.global [%0], [%1], 16;" :: "r"(s), "l"(g))
#define CP_COMMIT() asm volatile("cp.async.commit_group;" ::: "memory")
#define LDSM4(r, a) \
    asm volatile("ldmatrix.sync.aligned.m8n8.x4.shared.b16 {%0,%1,%2,%3}, [%4];" \
        : "=r"((r)[0]), "=r"((r)[1]), "=r"((r)[2]), "=r"((r)[3]) : "r"(a))
#define MMA16(c, a, b0, b1) \
    asm volatile("mma.sync.aligned.m16n8k16.row.col.f32.f16.f16.f32 " \
        "{%0,%1,%2,%3}, {%4,%5,%6,%7}, {%8,%9}, {%0,%1,%2,%3};" \
        : "+f"((c)[0]), "+f"((c)[1]), "+f"((c)[2]), "+f"((c)[3]) \
        : "r"((a)[0]), "r"((a)[1]), "r"((a)[2]), "r"((a)[3]), "r"(b0), "r"(b1))

// ============================================================================
// fp16 HMMA GEMM: D[m,n] = sum_k A[m,k]*B[n,k]; 128x128 CTA tile, 4 warps,
// 64x64 warp tiles, K chunk 64, 3-stage cp.async pipeline, one sync per chunk.
// mode 0: fp32 C[((m>>10)*mMul + mOff + m&1023)*ldC + n] + bias[n]
// mode 1: fp32 C[((n>>10)*ldC + m)*1024 + (n&1023)]      + bias[m]
// mode 2: fp16 C, row mapping of mode 0
// mode 3: dual: col<512 -> fp16 Cv (ld 512, bias[n]); col>=512 -> fp32 Cv2
//         (ld 256, bias2[lvl*256 + n-512]),  lvl = (m0>>10)&1
// mode 4: fp16 C, mapping of mode 1
// ============================================================================
#define GEMM_SMEM 98304
__global__ __launch_bounds__(128) void gemm_tc(
    const __half* __restrict__ Ah,
    const __half* __restrict__ B,
    const float* __restrict__ bias, void* __restrict__ Cv,
    int K, int mode, int mMul, int mOff, int ldC,
    long zA, long zB, int zBias, int zOffMul, int biasLvl,
    void* __restrict__ Cv2, const float* __restrict__ bias2)
{
    extern __shared__ __align__(16) char smem[];
    const uint32_t sb = smem_u32(smem);
    const int tid = threadIdx.x;
    const int z = blockIdx.z;
    Ah += (size_t)z * zA; B += (size_t)z * zB;
    const int m0 = blockIdx.y * 128, n0 = blockIdx.x * 128;
    bias += z * zBias + ((m0 >> 10) & 1) * biasLvl;
    const int mOffE = mOff + z * zOffMul;
    const int warp = tid >> 5, lane = tid & 31;
    const int wm = warp >> 1, wn = warp & 1;     // 2x2 warp grid, 64x64 tiles

    const int arow_l = lane & 15, akg_l = lane >> 4;
    const int nr = (lane & 7) + ((lane & 16) >> 1);
    const int bkg_l = (lane >> 3) & 1;

    float acc[4][8][4];
    #pragma unroll
    for (int i = 0; i < 4; ++i)
        #pragma unroll
        for (int j = 0; j < 8; ++j)
            #pragma unroll
            for (int k = 0; k < 4; ++k) acc[i][j][k] = 0.f;

    const int nC = K >> 6;     // K chunks of 64

    auto load_stage = [&](int c) {
        const uint32_t stb = sb + (uint32_t)(c % 3) * 32768u;
        const int k0 = c << 6;
        #pragma unroll
        for (int gi = 0; gi < 8; ++gi) {
            int g = tid + gi * 128;             // 1024 16B-chunks per tile
            int row = g >> 3, c8 = g & 7;       // 8 chunks per 128B row
            uint32_t so = (uint32_t)(row * 128 + ((c8 ^ (row & 7)) << 4));
            CP16(stb +         so, Ah + (size_t)(m0 + row) * K + k0 + c8 * 8);
            CP16(stb + 16384 + so, B  + (size_t)(n0 + row) * K + k0 + c8 * 8);
        }
        CP_COMMIT();
    };

    load_stage(0);
    if (nC > 1) load_stage(1);
    for (int c = 0; c < nC; ++c) {
        if (c + 1 < nC) asm volatile("cp.async.wait_group 1;" ::: "memory");
        else            asm volatile("cp.async.wait_group 0;" ::: "memory");
        __syncthreads();
        if (c + 2 < nC) load_stage(c + 2);
        const uint32_t stb = sb + (uint32_t)(c % 3) * 32768u;
        #pragma unroll
        for (int kk = 0; kk < 4; ++kk) {
            uint32_t ah[4][4];
            #pragma unroll
            for (int mf = 0; mf < 4; ++mf) {
                int arow = wm * 64 + mf * 16 + arow_l;
                uint32_t ad = stb + (uint32_t)(arow * 128 +
                              ((((kk << 1) + akg_l) ^ (arow_l & 7)) << 4));
                LDSM4(ah[mf], ad);
            }
            #pragma unroll
            for (int np = 0; np < 4; ++np) {
                int brow = wn * 64 + np * 16 + nr;
                uint32_t bd = stb + 16384u + (uint32_t)(brow * 128 +
                              ((((kk << 1) + bkg_l) ^ (nr & 7)) << 4));
                uint32_t bh[4];
                LDSM4(bh, bd);
                #pragma unroll
                for (int half = 0; half < 2; ++half) {
                    uint32_t b0 = bh[half*2], b1 = bh[half*2+1];
                    int nj = np * 2 + half;
                    #pragma unroll
                    for (int mf = 0; mf < 4; ++mf)
                        MMA16(acc[mf][nj], ah[mf], b0, b1);
                }
            }
        }
    }

    // ---- epilogue ----
    const int tq = lane >> 2, tr2 = (lane & 3) * 2;
    const int lvlB = ((m0 >> 10) & 1) * 256;
    #pragma unroll
    for (int mf = 0; mf < 4; ++mf) {
        #pragma unroll
        for (int nj = 0; nj < 8; ++nj) {
            int mrow = m0 + wm * 64 + mf * 16 + tq;
            int col  = n0 + wn * 64 + nj * 8 + tr2;
            float* a0 = acc[mf][nj];
            if (mode == 1 || mode == 4) {
                float bm0 = bias[mrow], bm1 = bias[mrow + 8];
                size_t base = ((size_t)((col >> 10) * ldC)) * 1024 + (col & 1023);
                if (mode == 1) {
                    float* C = (float*)Cv;
                    *(float2*)(C + base + (size_t)mrow       * 1024) = make_float2(a0[0] + bm0, a0[1] + bm0);
                    *(float2*)(C + base + (size_t)(mrow + 8) * 1024) = make_float2(a0[2] + bm1, a0[3] + bm1);
                } else {
                    __half* C = (__half*)Cv;
                    *(__half2*)(C + base + (size_t)mrow       * 1024) = __floats2half2_rn(a0[0] + bm0, a0[1] + bm0);
                    *(__half2*)(C + base + (size_t)(mrow + 8) * 1024) = __floats2half2_rn(a0[2] + bm1, a0[3] + bm1);
                }
            } else if (mode == 3) {
                int rp0 = mrow, rp1 = mrow + 8;
                if (col < 512) {
                    __half* C = (__half*)Cv;
                    float b0 = bias[col], b1 = bias[col + 1];
                    *(__half2*)(C + (size_t)rp0 * 512 + col) =
                        __floats2half2_rn(a0[0] + b0, a0[1] + b1);
                    *(__half2*)(C + (size_t)rp1 * 512 + col) =
                        __floats2half2_rn(a0[2] + b0, a0[3] + b1);
                } else {
                    float* C = (float*)Cv2;
                    int cc = col - 512;
                    float b0 = bias2[lvlB + cc], b1 = bias2[lvlB + cc + 1];
                    *(float2*)(C + (size_t)rp0 * 256 + cc) = make_float2(a0[0] + b0, a0[1] + b1);
                    *(float2*)(C + (size_t)rp1 * 256 + cc) = make_float2(a0[2] + b0, a0[3] + b1);
                }
            } else {
                float b0 = bias[col], b1 = bias[col + 1];
                int rp0 = (mrow >> 10) * mMul + mOffE + (mrow & 1023);
                int m2 = mrow + 8;
                int rp1 = (m2 >> 10) * mMul + mOffE + (m2 & 1023);
                if (mode == 0) {
                    float* C = (float*)Cv;
                    *(float2*)(C + (size_t)rp0 * ldC + col) = make_float2(a0[0] + b0, a0[1] + b1);
                    *(float2*)(C + (size_t)rp1 * ldC + col) = make_float2(a0[2] + b0, a0[3] + b1);
                } else {
                    __half* C = (__half*)Cv;
                    *(__half2*)(C + (size_t)rp0 * ldC + col) =
                        __floats2half2_rn(a0[0] + b0, a0[1] + b1);
                    *(__half2*)(C + (size_t)rp1 * ldC + col) =
                        __floats2half2_rn(a0[2] + b0, a0[3] + b1);
                }
            }
        }
    }
}

// ---------------- prep: transpose both inputs (z=16) ----------------
__global__ void prep_input2(const float* __restrict__ iv, const float* __restrict__ ii,
                            __half* __restrict__ xh)
{
    __shared__ float tl[32][33];
    int zz = blockIdx.z;
    int b = zz & 7;
    const float* in = (zz < 8) ? iv : ii;
    __half* out = xh + (size_t)(zz >> 3) * 8192 * 768;
    int c0 = blockIdx.y * 32, hw0 = blockIdx.x * 32;
    const float* ip = in + ((size_t)b * CC + c0) * HWW + hw0;
    #pragma unroll
    for (int j = 0; j < 4; ++j)
        tl[threadIdx.y + j*8][threadIdx.x] = ip[(size_t)(threadIdx.y + j*8) * HWW + threadIdx.x];
    __syncthreads();
    #pragma unroll
    for (int j = 0; j < 4; ++j) {
        int hw = hw0 + threadIdx.y + j*8;
        int cc = c0 + threadIdx.x;
        size_t o = ((size_t)b * HWW + hw) * CC + cc;
        out[o] = __float2half_rn(tl[threadIdx.x][threadIdx.y + j*8]);
    }
}

// ---------------- one-shot weight prep ----------------
__global__ void prep_weights(
    const float* __restrict__ wv,    const float* __restrict__ wi,
    const float* __restrict__ w_val, const float* __restrict__ w_out,
    const float* __restrict__ w_off, const float* __restrict__ w_attn,
    const float* __restrict__ wc,
    const float* __restrict__ bv,    const float* __restrict__ bi,
    __half* __restrict__ w1h,  __half* __restrict__ wvoa,
    __half* __restrict__ wouth,
    __half* __restrict__ wch,
    float* __restrict__ b1)
{
    int i = blockIdx.x * 256 + threadIdx.x;
    if (i < 786432) {
        w1h[i] = __float2half_rn(i < 393216 ? wv[i] : wi[i - 393216]);
    } else if (i < 1179648) {
        int j = i - 786432;                // combined [w_val ; w_oa]
        int r = j >> 9, c = j & 511;
        float v;
        if (r < 512) v = w_val[r * 512 + c];
        else {
            int rr = r - 512;
            v = (rr < 128) ? w_off[rr * 512 + c] : ((rr < 192) ? w_attn[(rr - 128) * 512 + c] : 0.f);
        }
        wvoa[j] = __float2half_rn(v);
    } else if (i < 1441792) {
        int j = i - 1179648;
        wouth[j] = __float2half_rn(w_out[j]);
    } else if (i < 2228224) {
        int j = i - 1441792;
        wch[j] = __float2half_rn(wc[j]);
    } else if (i < 2229248) {
        int j = i - 2228224;
        b1[j] = (j < 512) ? bv[j] : bi[j - 512];
    }
}

// ---------------- lep[lvl][n] = le[lvl] . Woa[n] + boa[n]  (fp32, exact) -------
__global__ void leproj_k(const float* __restrict__ le,
                         const float* __restrict__ w_off, const float* __restrict__ w_attn,
                         const float* __restrict__ b_off, const float* __restrict__ b_attn,
                         float* __restrict__ lep)
{
    int lvl = blockIdx.x, n = threadIdx.x;   // 2 x 256
    const float* l = le + lvl * 512;
    float s = 0.f;
    if (n < 128) {
        s = b_off[n];
        const float* w = w_off + n * 512;
        for (int d = 0; d < 512; ++d) s = fmaf(l[d], w[d], s);
    } else if (n < 192) {
        s = b_attn[n - 128];
        const float* w = w_attn + (n - 128) * 512;
        for (int d = 0; d < 512; ++d) s = fmaf(l[d], w[d], s);
    }
    lep[lvl * 256 + n] = s;
}

// ---------------- GN stats over seq-major fp16 pre; group = (be, 16 ch) ----------------
__global__ void gn_stats_seq(const __half* __restrict__ x, float* __restrict__ stats)
{
    int be = blockIdx.y, g = blockIdx.x;
    int t = threadIdx.x;
    const __half* base = x + (size_t)be * 1024 * 512 + g * 16 + (t & 1) * 8;
    float s = 0.f, sq = 0.f;
    #pragma unroll
    for (int it = 0; it < 8; ++it) {
        uint4 raw = *(const uint4*)(base + (size_t)((t >> 1) + it * 128) * 512);
        float2 a = __half22float2(*(__half2*)&raw.x);
        float2 b = __half22float2(*(__half2*)&raw.y);
        float2 cc = __half22float2(*(__half2*)&raw.z);
        float2 d = __half22float2(*(__half2*)&raw.w);
        s  += a.x + a.y + b.x + b.y + cc.x + cc.y + d.x + d.y;
        sq += a.x*a.x + a.y*a.y + b.x*b.x + b.y*b.y + cc.x*cc.x + cc.y*cc.y + d.x*d.x + d.y*d.y;
    }
    __shared__ float red[16];
    for (int o = 16; o > 0; o >>= 1) {
        s  += __shfl_down_sync(0xffffffffu, s,  o);
        sq += __shfl_down_sync(0xffffffffu, sq, o);
    }
    if ((t & 31) == 0) { red[t >> 5] = s; red[8 + (t >> 5)] = sq; }
    __syncthreads();
    if (t < 32) {
        s  = (t < 8) ? red[t]     : 0.f;
        sq = (t < 8) ? red[8 + t] : 0.f;
        for (int o = 4; o > 0; o >>= 1) {
            s  += __shfl_down_sync(0xffffffffu, s,  o);
            sq += __shfl_down_sync(0xffffffffu, sq, o);
        }
        if (t == 0) {
            float mean = s * (1.f/16384.f);
            float var  = sq * (1.f/16384.f) - mean * mean;
            stats[(be*32+g)*2]   = mean;
            stats[(be*32+g)*2+1] = rsqrtf(var + 1e-5f);
        }
    }
}

// ---------------- GN1 finish: fp16 pre -> src fp16 (8 elem/thread) ----------------
__global__ void gn1_finish2(const __half* __restrict__ pre, const float* __restrict__ stats,
    const float* __restrict__ gv, const float* __restrict__ bev,
    const float* __restrict__ gi, const float* __restrict__ bei,
    __half* __restrict__ sh)
{
    size_t e = ((size_t)blockIdx.x * 256 + threadIdx.x) * 8;
    int row = (int)(e >> 9), d = (int)(e & 511);
    int be = row >> 10, lvl = be & 1;
    float mean = stats[(be * 32 + (d >> 4)) * 2];
    float rstd = stats[(be * 32 + (d >> 4)) * 2 + 1];
    const float* gam = lvl ? gi : gv;
    const float* bet = lvl ? bei : bev;
    uint4 raw = *(const uint4*)(pre + e);
    __half* rp = (__half*)&raw;
    __half hh[8];
    #pragma unroll
    for (int k = 0; k < 8; ++k)
        hh[k] = __float2half_rn((__half2float(rp[k]) - mean) * rstd * gam[d + k] + bet[d + k]);
    *(uint4*)(sh + e) = *(uint4*)hh;
}

// ---------------- deformable sampling (fused softmax), half2 loads ----------------
__global__ __launch_bounds__(256) void msda_sample(
    const __half* __restrict__ vproj, const float* __restrict__ oa,
    __half* __restrict__ msh)
{
    int bq = blockIdx.x;
    int b = bq >> 11;
    int hw = bq & 1023;
    float refx = ((hw & 31) + 0.5f) * (1.f/32.f);
    float refy = ((hw >> 5) + 0.5f) * (1.f/32.f);
    __shared__ float sx[64], sy[64], sw[64];
    int t = threadIdx.x;   // 256
    const float* row = oa + (size_t)bq * 256;
    if (t < 64) {
        sx[t] = (refx + row[t*2]   * (1.f/32.f)) * 32.f - 0.5f;
        sy[t] = (refy + row[t*2+1] * (1.f/32.f)) * 32.f - 0.5f;
        float lg = row[128 + t];
        float m = lg;
        #pragma unroll
        for (int o = 1; o < 8; o <<= 1) m = fmaxf(m, __shfl_xor_sync(0xffffffffu, m, o));
        float ex = expf(lg - m);
        float s = ex;
        #pragma unroll
        for (int o = 1; o < 8; o <<= 1) s += __shfl_xor_sync(0xffffffffu, s, o);
        sw[t] = ex / s;
    }
    __syncthreads();
    int head = t >> 5, c2 = t & 31;       // 8 heads x 32 half2-channels
    const __half2* vb = (const __half2*)(vproj + (size_t)b * LQQ * DD) + head * 32 + c2;
    float accx = 0.f, accy = 0.f;
    #pragma unroll
    for (int lp = 0; lp < 8; lp++) {
        int l = lp >> 2;
        float xs = sx[head*8+lp], ys = sy[head*8+lp], w = sw[head*8+lp];
        float x0f = floorf(xs), y0f = floorf(ys);
        float fx = xs - x0f, fy = ys - y0f;
        int x0 = (int)x0f, y0 = (int)y0f;
        const __half2* vl = vb + (size_t)l * HWW * 256;
        bool xa = (unsigned)x0 < 32u, xb = (unsigned)(x0+1) < 32u;
        bool ya = (unsigned)y0 < 32u, yb = (unsigned)(y0+1) < 32u;
        float2 z2 = make_float2(0.f, 0.f);
        float2 v00 = (ya && xa) ? __half22float2(vl[(size_t)(y0*32 + x0)      * 256]) : z2;
        float2 v01 = (ya && xb) ? __half22float2(vl[(size_t)(y0*32 + x0 + 1)  * 256]) : z2;
        float2 v10 = (yb && xa) ? __half22float2(vl[(size_t)(y0*32 + x0 + 32) * 256]) : z2;
        float2 v11 = (yb && xb) ? __half22float2(vl[(size_t)(y0*32 + x0 + 33) * 256]) : z2;
        float w00 = (1.f-fy)*(1.f-fx), w01 = (1.f-fy)*fx, w10 = fy*(1.f-fx), w11 = fy*fx;
        accx = fmaf(w, v00.x*w00 + v01.x*w01 + v10.x*w10 + v11.x*w11, accx);
        accy = fmaf(w, v00.y*w00 + v01.y*w01 + v10.y*w10 + v11.y*w11, accy);
    }
    ((__half2*)msh)[(size_t)bq * 256 + head * 32 + c2] = __floats2half2_rn(accx, accy);
}

// ---------------- residual + LN: src recomputed from fp16 pre + stats ----------------
__global__ void ln_res(const __half* __restrict__ pre, const float* __restrict__ stats,
                       const float* __restrict__ gv, const float* __restrict__ bev,
                       const float* __restrict__ gi, const float* __restrict__ bei,
                       const __half* __restrict__ att,
                       const float* __restrict__ g, const float* __restrict__ be,
                       __half* __restrict__ cath)
{
    int grow = blockIdx.x;            // b*2048 + lvl*1024 + hw
    size_t base = (size_t)grow * DD;
    int t = threadIdx.x;              // 256
    int bee = grow >> 10, lvl = bee & 1;
    const float* gam = lvl ? gi : gv;
    const float* bet = lvl ? bei : bev;
    float mean0 = stats[(bee * 32 + (t >> 4)) * 2];
    float rstd0 = stats[(bee * 32 + (t >> 4)) * 2 + 1];
    int t2 = t + 256;
    float mean1 = stats[(bee * 32 + (t2 >> 4)) * 2];
    float rstd1 = stats[(bee * 32 + (t2 >> 4)) * 2 + 1];
    float s0 = (__half2float(pre[base + t])  - mean0) * rstd0 * gam[t]  + bet[t];
    float s1 = (__half2float(pre[base + t2]) - mean1) * rstd1 * gam[t2] + bet[t2];
    float v0 = s0 + __half2float(att[base + t]);
    float v1 = s1 + __half2float(att[base + t2]);
    float s = v0 + v1, sq = v0*v0 + v1*v1;
    __shared__ float red[16];
    for (int o = 16; o > 0; o >>= 1) {
        s  += __shfl_down_sync(0xffffffffu, s,  o);
        sq += __shfl_down_sync(0xffffffffu, sq, o);
    }
    if ((t & 31) == 0) { red[t >> 5] = s; red[8 + (t >> 5)] = sq; }
    __syncthreads();
    if (t < 32) {
        s  = (t < 8) ? red[t]     : 0.f;
        sq = (t < 8) ? red[8 + t] : 0.f;
        for (int o = 4; o > 0; o >>= 1) {
            s  += __shfl_down_sync(0xffffffffu, s,  o);
            sq += __shfl_down_sync(0xffffffffu, sq, o);
        }
        if (t == 0) { red[0] = s; red[8] = sq; }
    }
    __syncthreads();
    float mu   = red[0] * (1.f/512.f);
    float var  = red[8] * (1.f/512.f) - mu * mu;
    float rstd = rsqrtf(var + 1e-5f);
    int b = grow >> 11, hw = grow & 1023;
    size_t obase = ((size_t)b * 1024 + hw) * 1024 + lvl * 512;
    cath[obase + t]       = __float2half_rn((v0 - mu) * rstd * g[t]  + be[t]);
    cath[obase + t + 256] = __float2half_rn((v1 - mu) * rstd * g[t2] + be[t2]);
}

// ---------------- GN stats: contiguous fp16 groups (conv2 output) ----------------
__global__ void gn_stats_h(const __half* __restrict__ x, float* __restrict__ stats, int groupElems)
{
    int idx = blockIdx.y * gridDim.x + blockIdx.x;
    const __half* p = x + (size_t)idx * groupElems;
    float s = 0.f, sq = 0.f;
    for (int i = threadIdx.x * 8; i < groupElems; i += blockDim.x * 8) {
        uint4 raw = *(const uint4*)(p + i);
        float2 a = __half22float2(*(__half2*)&raw.x);
        float2 b = __half22float2(*(__half2*)&raw.y);
        float2 c = __half22float2(*(__half2*)&raw.z);
        float2 d = __half22float2(*(__half2*)&raw.w);
        s  += a.x + a.y + b.x + b.y + c.x + c.y + d.x + d.y;
        sq += a.x*a.x + a.y*a.y + b.x*b.x + b.y*b.y + c.x*c.x + c.y*c.y + d.x*d.x + d.y*d.y;
    }
    __shared__ float red[16];
    int t = threadIdx.x;
    for (int o = 16; o > 0; o >>= 1) {
        s  += __shfl_down_sync(0xffffffffu, s,  o);
        sq += __shfl_down_sync(0xffffffffu, sq, o);
    }
    if ((t & 31) == 0) { red[t >> 5] = s; red[8 + (t >> 5)] = sq; }
    __syncthreads();
    if (t < 32) {
        s  = (t < 8) ? red[t]     : 0.f;
        sq = (t < 8) ? red[8 + t] : 0.f;
        for (int o = 4; o > 0; o >>= 1) {
            s  += __shfl_down_sync(0xffffffffu, s,  o);
            sq += __shfl_down_sync(0xffffffffu, sq, o);
        }
        if (t == 0) {
            float inv = 1.f / (float)groupElems;
            float mean = s * inv;
            stats[idx*2]   = mean;
            stats[idx*2+1] = rsqrtf(sq * inv - mean * mean + 1e-5f);
        }
    }
}

__global__ void gn2_finish(const __half* __restrict__ x, const float* __restrict__ stats,
    const float* __restrict__ gc, const float* __restrict__ bec, float* __restrict__ out)
{
    size_t i2 = ((size_t)blockIdx.x * blockDim.x + threadIdx.x) * 2;
    int hwch = (int)(i2 >> 10);
    int ch = hwch % 768;
    int b  = hwch / 768;
    int g  = ch / 24;
    float mean = stats[(b*32 + g) * 2];
    float rstd = stats[(b*32 + g) * 2 + 1];
    float2 v = __half22float2(*(const __half2*)(x + i2));
    float gg = gc[ch], bb = bec[ch];
    *(float2*)(out + i2) = make_float2((v.x - mean) * rstd * gg + bb,
                                       (v.y - mean) * rstd * gg + bb);
}

// ---------------- launcher ----------------
#define SYM(T, v, s) T v; cudaGetSymbolAddress((void**)&v, s)
extern "C" void kernel_launch(void* const* d_in, const int* in_sizes, int n_in,
                              void* d_out, int out_size)
{
    const float* input_v = (const float*)d_in[0];
    const float* input_i = (const float*)d_in[1];
    const float* wv      = (const float*)d_in[2];
    const float* bv      = (const float*)d_in[3];
    const float* gv      = (const float*)d_in[4];
    const float* bev     = (const float*)d_in[5];
    const float* wi      = (const float*)d_in[6];
    const float* bi      = (const float*)d_in[7];
    const float* gi      = (const float*)d_in[8];
    const float* bei     = (const float*)d_in[9];
    const float* le      = (const float*)d_in[10];
    const float* w_off   = (const float*)d_in[11];
    const float* b_off   = (const float*)d_in[12];
    const float* w_attn  = (const float*)d_in[13];
    const float* b_attn  = (const float*)d_in[14];
    const float* w_val   = (const float*)d_in[15];
    const float* b_val   = (const float*)d_in[16];
    const float* w_out   = (const float*)d_in[17];
    const float* b_out   = (const float*)d_in[18];
    const float* ln_g    = (const float*)d_in[19];
    const float* ln_b    = (const float*)d_in[20];
    const float* wc      = (const float*)d_in[21];
    const float* bc      = (const float*)d_in[22];
    const float* gc      = (const float*)d_in[23];
    const float* bec     = (const float*)d_in[24];

    SYM(__half*, xth,  g_xth);
    SYM(__half*, w1h,  g_w1h);  SYM(__half*, wvoa, g_wvoa);
    SYM(__half*, wouth,g_wouth);
    SYM(__half*, wch,  g_wch_);
    SYM(__half*, preh, g_preh);
    SYM(__half*, srch, g_srch);
    SYM(__half*, msh,  g_msh);
    SYM(__half*, cath, g_cath); SYM(__half*, vph,  g_vph);
    SYM(__half*, attno, g_attnoh);
    SYM(__half*, conv2h, g_conv2h);
    SYM(float*, oa,    g_oa4);
    SYM(float*, lep,   g_lep);    SYM(float*, b1,    g_b1);
    SYM(float*, st1,   g_stats1); SYM(float*, st2,   g_stats2);
    size_t XT = (size_t)8192*768;

    cudaFuncSetAttribute(gemm_tc, cudaFuncAttributeMaxDynamicSharedMemorySize, GEMM_SMEM);

    // prep
    prep_weights<<<8708, 256>>>(wv, wi, w_val, w_out, w_off, w_attn, wc,
                                bv, bi, w1h, wvoa, wouth, wch, b1);
    leproj_k<<<2, 256>>>(le, w_off, w_attn, b_off, b_attn, lep);
    prep_input2<<<dim3(32, 24, 16), dim3(32, 8)>>>(input_v, input_i, xth);

    // conv1 (v+i, z planes): fp16 D -> rows (b, lvl, hw)
    gemm_tc<<<dim3(4, 64, 2), 128, GEMM_SMEM>>>(xth, w1h, b1, preh,
        768, 2, 2048, 0, 512, (long)XT, 393216L, 512, 1024, 0, nullptr, nullptr);
    // GN1
    gn_stats_seq<<<dim3(32, 16), 256>>>(preh, st1);
    gn1_finish2<<<4096, 256>>>(preh, st1, gv, bev, gi, bei, srch);
    // fused vproj+oa projection [dual output]
    gemm_tc<<<dim3(6, 128), 128, GEMM_SMEM>>>(srch, wvoa, b_val, vph,
        512, 3, 1024, 0, 512, 0L, 0L, 0, 0, 0, oa, lep);
    // sampling (softmax fused)
    msda_sample<<<MROWS, 256>>>(vph, oa, msh);
    // output projection [fp16 out]
    gemm_tc<<<dim3(4, 128), 128, GEMM_SMEM>>>(msh, wouth, b_out, attno,
        512, 2, 1024, 0, 512, 0L, 0L, 0, 0, 0, nullptr, nullptr);
    // residual + LN (src recomputed from preh) -> cat fp16
    ln_res<<<MROWS, 256>>>(preh, st1, gv, bev, gi, bei, attno, ln_g, ln_b, cath);
    // conv2: fp16 D -> (b, o, hw)
    gemm_tc<<<dim3(64, 6), 128, GEMM_SMEM>>>(wch, cath, bc, conv2h,
        1024, 4, 0, 0, 768, 0L, 0L, 0, 0, 0, nullptr, nullptr);
    // final GN
    gn_stats_h<<<dim3(32, BB), 256>>>(conv2h, st2, 24 * HWW);
    gn2_finish<<<12288, 256>>>(conv2h, st2, gc, bec, (float*)d_out);
}

// round 16
// speedup vs baseline: 1.0453x; 1.0453x over previous
#include <cuda_runtime.h>
#include <cuda_fp16.h>
#include <cstdint>

#define BB   8
#define CC   768
#define DD   512
#define HWW  1024
#define LQQ  2048
#define MROWS (BB*LQQ)   // 16384

// ---------------- scratch (device globals) ----------------
__device__ uint4 g_xth [2][8192*768/8];
__device__ uint4 g_w1h [2*512*768/8];                 // conv1 weights v|i
__device__ uint4 g_wvoa[768*512/8];                   // [w_val(512) ; w_oa(256)]
__device__ uint4 g_wouth[512*512/8];
__device__ uint4 g_wch_[768*1024/8];
__device__ uint4 g_preh[MROWS*512/8];                 // conv1 out fp16
__device__ uint4 g_srch[MROWS*512/8];
__device__ uint4 g_msh[MROWS*512/8];
__device__ uint4 g_cath[8192*1024/8];
__device__ uint4 g_vph [MROWS*512/8];                 // vproj fp16
__device__ uint4 g_attnoh[MROWS*512/8];               // attn out fp16
__device__ uint4 g_conv2h[BB*CC*HWW/8];               // conv2 out fp16
__device__ uint4 g_oah [MROWS*256/8];                 // offsets+logits fp16
__device__ float  g_lep  [512];                       // le@Woa^T + boa, [lvl][256]
__device__ float  g_b1   [1024];                      // conv1 bias v|i
__device__ float  g_stats1[BB*2*32*2];
__device__ float  g_stats2[BB*32*2];

// ---------------- PTX helpers (sm_80-compatible ISA only) ----------------
__device__ __forceinline__ uint32_t smem_u32(const void* p) {
    uint32_t a;
    asm("{ .reg .u64 t; cvta.to.shared.u64 t, %1; cvt.u32.u64 %0, t; }" : "=r"(a) : "l"(p));
    return a;
}
#define CP16(s, g) \
    asm volatile("cp.async.cg.shared.global [%0], [%1], 16;" :: "r"(s), "l"(g))
#define CP_COMMIT() asm volatile("cp.async.commit_group;" ::: "memory")
#define LDSM4(r, a) \
    asm volatile("ldmatrix.sync.aligned.m8n8.x4.shared.b16 {%0,%1,%2,%3}, [%4];" \
        : "=r"((r)[0]), "=r"((r)[1]), "=r"((r)[2]), "=r"((r)[3]) : "r"(a))
#define MMA16(c, a, b0, b1) \
    asm volatile("mma.sync.aligned.m16n8k16.row.col.f32.f16.f16.f32 " \
        "{%0,%1,%2,%3}, {%4,%5,%6,%7}, {%8,%9}, {%0,%1,%2,%3};" \
        : "+f"((c)[0]), "+f"((c)[1]), "+f"((c)[2]), "+f"((c)[3]) \
        : "r"((a)[0]), "r"((a)[1]), "r"((a)[2]), "r"((a)[3]), "r"(b0), "r"(b1))

// ============================================================================
// fp16 HMMA GEMM: D[m,n] = sum_k A[m,k]*B[n,k]; 128x128 CTA tile, 8 warps,
// 32x64 warp tiles, K chunk 64, 3-stage cp.async pipeline, one sync per chunk.
// mode 0: fp32 C[((m>>10)*mMul + mOff + m&1023)*ldC + n] + bias[n]
// mode 1: fp32 C[((n>>10)*ldC + m)*1024 + (n&1023)]      + bias[m]
// mode 2: fp16 C, row mapping of mode 0
// mode 3: dual fp16: col<512 -> Cv (ld 512, bias[n]); col>=512 -> Cv2
//         (ld 256, bias2[lvl*256 + n-512]),  lvl = (m0>>10)&1
// mode 4: fp16 C, mapping of mode 1
// ============================================================================
#define GEMM_SMEM 98304
__global__ __launch_bounds__(256) void gemm_tc(
    const __half* __restrict__ Ah,
    const __half* __restrict__ B,
    const float* __restrict__ bias, void* __restrict__ Cv,
    int K, int mode, int mMul, int mOff, int ldC,
    long zA, long zB, int zBias, int zOffMul, int biasLvl,
    void* __restrict__ Cv2, const float* __restrict__ bias2)
{
    extern __shared__ __align__(16) char smem[];
    const uint32_t sb = smem_u32(smem);
    const int tid = threadIdx.x;
    const int z = blockIdx.z;
    Ah += (size_t)z * zA; B += (size_t)z * zB;
    const int m0 = blockIdx.y * 128, n0 = blockIdx.x * 128;
    bias += z * zBias + ((m0 >> 10) & 1) * biasLvl;
    const int mOffE = mOff + z * zOffMul;
    const int warp = tid >> 5, lane = tid & 31;
    const int wm = warp >> 1, wn = warp & 1;   // 4x2 warp grid, 32x64 tiles

    const int arow_l = lane & 15, akg_l = lane >> 4;
    const int nr = (lane & 7) + ((lane & 16) >> 1);
    const int bkg_l = (lane >> 3) & 1;

    float acc[2][8][4];
    #pragma unroll
    for (int i = 0; i < 2; ++i)
        #pragma unroll
        for (int j = 0; j < 8; ++j)
            #pragma unroll
            for (int k = 0; k < 4; ++k) acc[i][j][k] = 0.f;

    const int nC = K >> 6;     // K chunks of 64

    auto load_stage = [&](int c) {
        const uint32_t stb = sb + (uint32_t)(c % 3) * 32768u;
        const int k0 = c << 6;
        #pragma unroll
        for (int gi = 0; gi < 4; ++gi) {
            int g = tid + gi * 256;             // 1024 16B-chunks per tile
            int row = g >> 3, c8 = g & 7;       // 8 chunks per 128B row
            uint32_t so = (uint32_t)(row * 128 + ((c8 ^ (row & 7)) << 4));
            CP16(stb +         so, Ah + (size_t)(m0 + row) * K + k0 + c8 * 8);
            CP16(stb + 16384 + so, B  + (size_t)(n0 + row) * K + k0 + c8 * 8);
        }
        CP_COMMIT();
    };

    load_stage(0);
    if (nC > 1) load_stage(1);
    for (int c = 0; c < nC; ++c) {
        if (c + 1 < nC) asm volatile("cp.async.wait_group 1;" ::: "memory");
        else            asm volatile("cp.async.wait_group 0;" ::: "memory");
        __syncthreads();
        if (c + 2 < nC) load_stage(c + 2);
        const uint32_t stb = sb + (uint32_t)(c % 3) * 32768u;
        #pragma unroll
        for (int kk = 0; kk < 4; ++kk) {
            uint32_t ah[2][4];
            #pragma unroll
            for (int mf = 0; mf < 2; ++mf) {
                int arow = wm * 32 + mf * 16 + arow_l;
                uint32_t ad = stb + (uint32_t)(arow * 128 +
                              ((((kk << 1) + akg_l) ^ (arow_l & 7)) << 4));
                LDSM4(ah[mf], ad);
            }
            #pragma unroll
            for (int np = 0; np < 4; ++np) {
                int brow = wn * 64 + np * 16 + nr;
                uint32_t bd = stb + 16384u + (uint32_t)(brow * 128 +
                              ((((kk << 1) + bkg_l) ^ (nr & 7)) << 4));
                uint32_t bh[4];
                LDSM4(bh, bd);
                #pragma unroll
                for (int half = 0; half < 2; ++half) {
                    uint32_t b0 = bh[half*2], b1 = bh[half*2+1];
                    int nj = np * 2 + half;
                    #pragma unroll
                    for (int mf = 0; mf < 2; ++mf)
                        MMA16(acc[mf][nj], ah[mf], b0, b1);
                }
            }
        }
    }

    // ---- epilogue ----
    const int tq = lane >> 2, tr2 = (lane & 3) * 2;
    const int lvlB = ((m0 >> 10) & 1) * 256;
    #pragma unroll
    for (int mf = 0; mf < 2; ++mf) {
        #pragma unroll
        for (int nj = 0; nj < 8; ++nj) {
            int mrow = m0 + wm * 32 + mf * 16 + tq;
            int col  = n0 + wn * 64 + nj * 8 + tr2;
            float* a0 = acc[mf][nj];
            if (mode == 1 || mode == 4) {
                float bm0 = bias[mrow], bm1 = bias[mrow + 8];
                size_t base = ((size_t)((col >> 10) * ldC)) * 1024 + (col & 1023);
                if (mode == 1) {
                    float* C = (float*)Cv;
                    *(float2*)(C + base + (size_t)mrow       * 1024) = make_float2(a0[0] + bm0, a0[1] + bm0);
                    *(float2*)(C + base + (size_t)(mrow + 8) * 1024) = make_float2(a0[2] + bm1, a0[3] + bm1);
                } else {
                    __half* C = (__half*)Cv;
                    *(__half2*)(C + base + (size_t)mrow       * 1024) = __floats2half2_rn(a0[0] + bm0, a0[1] + bm0);
                    *(__half2*)(C + base + (size_t)(mrow + 8) * 1024) = __floats2half2_rn(a0[2] + bm1, a0[3] + bm1);
                }
            } else if (mode == 3) {
                int rp0 = mrow, rp1 = mrow + 8;
                if (col < 512) {
                    __half* C = (__half*)Cv;
                    float b0 = bias[col], b1 = bias[col + 1];
                    *(__half2*)(C + (size_t)rp0 * 512 + col) =
                        __floats2half2_rn(a0[0] + b0, a0[1] + b1);
                    *(__half2*)(C + (size_t)rp1 * 512 + col) =
                        __floats2half2_rn(a0[2] + b0, a0[3] + b1);
                } else {
                    __half* C = (__half*)Cv2;
                    int cc = col - 512;
                    float b0 = bias2[lvlB + cc], b1 = bias2[lvlB + cc + 1];
                    *(__half2*)(C + (size_t)rp0 * 256 + cc) =
                        __floats2half2_rn(a0[0] + b0, a0[1] + b1);
                    *(__half2*)(C + (size_t)rp1 * 256 + cc) =
                        __floats2half2_rn(a0[2] + b0, a0[3] + b1);
                }
            } else {
                float b0 = bias[col], b1 = bias[col + 1];
                int rp0 = (mrow >> 10) * mMul + mOffE + (mrow & 1023);
                int m2 = mrow + 8;
                int rp1 = (m2 >> 10) * mMul + mOffE + (m2 & 1023);
                if (mode == 0) {
                    float* C = (float*)Cv;
                    *(float2*)(C + (size_t)rp0 * ldC + col) = make_float2(a0[0] + b0, a0[1] + b1);
                    *(float2*)(C + (size_t)rp1 * ldC + col) = make_float2(a0[2] + b0, a0[3] + b1);
                } else {
                    __half* C = (__half*)Cv;
                    *(__half2*)(C + (size_t)rp0 * ldC + col) =
                        __floats2half2_rn(a0[0] + b0, a0[1] + b1);
                    *(__half2*)(C + (size_t)rp1 * ldC + col) =
                        __floats2half2_rn(a0[2] + b0, a0[3] + b1);
                }
            }
        }
    }
}

// ---------------- unified prep: weights | leproj | input transposes ----------------
// blocks [0,8708): weight conversion; [8708,8710): leproj; [8710,20998): transpose
__global__ void prep_all(
    const float* __restrict__ wv,    const float* __restrict__ wi,
    const float* __restrict__ w_val, const float* __restrict__ w_out,
    const float* __restrict__ w_off, const float* __restrict__ w_attn,
    const float* __restrict__ wc,
    const float* __restrict__ bv,    const float* __restrict__ bi,
    const float* __restrict__ le,
    const float* __restrict__ b_off, const float* __restrict__ b_attn,
    const float* __restrict__ iv,    const float* __restrict__ ii,
    __half* __restrict__ w1h,  __half* __restrict__ wvoa,
    __half* __restrict__ wouth, __half* __restrict__ wch,
    float* __restrict__ b1,    float* __restrict__ lep,
    __half* __restrict__ xh)
{
    __shared__ float tl[32][33];
    int bid = blockIdx.x;
    if (bid < 8708) {
        int i = bid * 256 + threadIdx.x;
        if (i < 786432) {
            w1h[i] = __float2half_rn(i < 393216 ? wv[i] : wi[i - 393216]);
        } else if (i < 1179648) {
            int j = i - 786432;                // combined [w_val ; w_oa]
            int r = j >> 9, c = j & 511;
            float v;
            if (r < 512) v = w_val[r * 512 + c];
            else {
                int rr = r - 512;
                v = (rr < 128) ? w_off[rr * 512 + c] : ((rr < 192) ? w_attn[(rr - 128) * 512 + c] : 0.f);
            }
            wvoa[j] = __float2half_rn(v);
        } else if (i < 1441792) {
            int j = i - 1179648;
            wouth[j] = __float2half_rn(w_out[j]);
        } else if (i < 2228224) {
            int j = i - 1441792;
            wch[j] = __float2half_rn(wc[j]);
        } else if (i < 2229248) {
            int j = i - 2228224;
            b1[j] = (j < 512) ? bv[j] : bi[j - 512];
        }
    } else if (bid < 8710) {
        int lvl = bid - 8708, n = threadIdx.x;
        const float* l = le + lvl * 512;
        float s = 0.f;
        if (n < 128) {
            s = b_off[n];
            const float* w = w_off + n * 512;
            for (int d = 0; d < 512; ++d) s = fmaf(l[d], w[d], s);
        } else if (n < 192) {
            s = b_attn[n - 128];
            const float* w = w_attn + (n - 128) * 512;
            for (int d = 0; d < 512; ++d) s = fmaf(l[d], w[d], s);
        }
        lep[lvl * 256 + n] = s;
    } else {
        int iid = bid - 8710;                 // [0, 12288)
        int bz = iid / 768, rest = iid % 768;
        int by = rest >> 5, bx = rest & 31;
        int b = bz & 7;
        const float* in = (bz < 8) ? iv : ii;
        __half* out = xh + (size_t)(bz >> 3) * 8192 * 768;
        int c0 = by * 32, hw0 = bx * 32;
        int tx = threadIdx.x & 31, ty = threadIdx.x >> 5;   // (32,8)
        const float* ip = in + ((size_t)b * CC + c0) * HWW + hw0;
        #pragma unroll
        for (int j = 0; j < 4; ++j)
            tl[ty + j*8][tx] = ip[(size_t)(ty + j*8) * HWW + tx];
        __syncthreads();
        #pragma unroll
        for (int j = 0; j < 4; ++j) {
            int hw = hw0 + ty + j*8;
            int cc = c0 + tx;
            size_t o = ((size_t)b * HWW + hw) * CC + cc;
            out[o] = __float2half_rn(tl[tx][ty + j*8]);
        }
    }
}

// ---------------- GN stats over seq-major fp16 pre; group = (be, 16 ch) ----------------
__global__ void gn_stats_seq(const __half* __restrict__ x, float* __restrict__ stats)
{
    int be = blockIdx.y, g = blockIdx.x;
    int t = threadIdx.x;
    const __half* base = x + (size_t)be * 1024 * 512 + g * 16 + (t & 1) * 8;
    float s = 0.f, sq = 0.f;
    #pragma unroll
    for (int it = 0; it < 8; ++it) {
        uint4 raw = *(const uint4*)(base + (size_t)((t >> 1) + it * 128) * 512);
        float2 a = __half22float2(*(__half2*)&raw.x);
        float2 b = __half22float2(*(__half2*)&raw.y);
        float2 cc = __half22float2(*(__half2*)&raw.z);
        float2 d = __half22float2(*(__half2*)&raw.w);
        s  += a.x + a.y + b.x + b.y + cc.x + cc.y + d.x + d.y;
        sq += a.x*a.x + a.y*a.y + b.x*b.x + b.y*b.y + cc.x*cc.x + cc.y*cc.y + d.x*d.x + d.y*d.y;
    }
    __shared__ float red[16];
    for (int o = 16; o > 0; o >>= 1) {
        s  += __shfl_down_sync(0xffffffffu, s,  o);
        sq += __shfl_down_sync(0xffffffffu, sq, o);
    }
    if ((t & 31) == 0) { red[t >> 5] = s; red[8 + (t >> 5)] = sq; }
    __syncthreads();
    if (t < 32) {
        s  = (t < 8) ? red[t]     : 0.f;
        sq = (t < 8) ? red[8 + t] : 0.f;
        for (int o = 4; o > 0; o >>= 1) {
            s  += __shfl_down_sync(0xffffffffu, s,  o);
            sq += __shfl_down_sync(0xffffffffu, sq, o);
        }
        if (t == 0) {
            float mean = s * (1.f/16384.f);
            float var  = sq * (1.f/16384.f) - mean * mean;
            stats[(be*32+g)*2]   = mean;
            stats[(be*32+g)*2+1] = rsqrtf(var + 1e-5f);
        }
    }
}

// ---------------- GN1 finish: fp16 pre -> src fp16 (8 elem/thread) ----------------
__global__ void gn1_finish2(const __half* __restrict__ pre, const float* __restrict__ stats,
    const float* __restrict__ gv, const float* __restrict__ bev,
    const float* __restrict__ gi, const float* __restrict__ bei,
    __half* __restrict__ sh)
{
    size_t e = ((size_t)blockIdx.x * 256 + threadIdx.x) * 8;
    int row = (int)(e >> 9), d = (int)(e & 511);
    int be = row >> 10, lvl = be & 1;
    float mean = stats[(be * 32 + (d >> 4)) * 2];
    float rstd = stats[(be * 32 + (d >> 4)) * 2 + 1];
    const float* gam = lvl ? gi : gv;
    const float* bet = lvl ? bei : bev;
    uint4 raw = *(const uint4*)(pre + e);
    __half* rp = (__half*)&raw;
    __half hh[8];
    #pragma unroll
    for (int k = 0; k < 8; ++k)
        hh[k] = __float2half_rn((__half2float(rp[k]) - mean) * rstd * gam[d + k] + bet[d + k]);
    *(uint4*)(sh + e) = *(uint4*)hh;
}

// ---------------- deformable sampling (fused softmax), 2 queries/block ----------------
__global__ __launch_bounds__(512) void msda_sample(
    const __half* __restrict__ vproj, const __half* __restrict__ oa,
    __half* __restrict__ msh)
{
    int bq0 = blockIdx.x * 2;
    __shared__ float sx[128], sy[128], sw[128];
    int t = threadIdx.x;   // 512
    if (t < 128) {
        int q = t >> 6, j = t & 63;
        int bq = bq0 + q;
        int hw = bq & 1023;
        float refx = ((hw & 31) + 0.5f) * (1.f/32.f);
        float refy = ((hw >> 5) + 0.5f) * (1.f/32.f);
        const __half* row = oa + (size_t)bq * 256;
        float2 off2 = __half22float2(*(const __half2*)(row + j * 2));
        sx[t] = (refx + off2.x * (1.f/32.f)) * 32.f - 0.5f;
        sy[t] = (refy + off2.y * (1.f/32.f)) * 32.f - 0.5f;
        float lg = __half2float(row[128 + j]);
        float m = lg;
        #pragma unroll
        for (int o = 1; o < 8; o <<= 1) m = fmaxf(m, __shfl_xor_sync(0xffffffffu, m, o));
        float ex = expf(lg - m);
        float s = ex;
        #pragma unroll
        for (int o = 1; o < 8; o <<= 1) s += __shfl_xor_sync(0xffffffffu, s, o);
        sw[t] = ex / s;
    }
    __syncthreads();
    int q = t >> 8, tt = t & 255;
    int bq = bq0 + q;
    int b = bq >> 11;
    int head = tt >> 5, c2 = tt & 31;     // 8 heads x 32 half2-channels
    const __half2* vb = (const __half2*)(vproj + (size_t)b * LQQ * DD) + head * 32 + c2;
    float accx = 0.f, accy = 0.f;
    #pragma unroll
    for (int lp = 0; lp < 8; lp++) {
        int l = lp >> 2;
        int si = q * 64 + head * 8 + lp;
        float xs = sx[si], ys = sy[si], w = sw[si];
        float x0f = floorf(xs), y0f = floorf(ys);
        float fx = xs - x0f, fy = ys - y0f;
        int x0 = (int)x0f, y0 = (int)y0f;
        const __half2* vl = vb + (size_t)l * HWW * 256;
        bool xa = (unsigned)x0 < 32u, xb = (unsigned)(x0+1) < 32u;
        bool ya = (unsigned)y0 < 32u, yb = (unsigned)(y0+1) < 32u;
        float2 z2 = make_float2(0.f, 0.f);
        float2 v00 = (ya && xa) ? __half22float2(vl[(size_t)(y0*32 + x0)      * 256]) : z2;
        float2 v01 = (ya && xb) ? __half22float2(vl[(size_t)(y0*32 + x0 + 1)  * 256]) : z2;
        float2 v10 = (yb && xa) ? __half22float2(vl[(size_t)(y0*32 + x0 + 32) * 256]) : z2;
        float2 v11 = (yb && xb) ? __half22float2(vl[(size_t)(y0*32 + x0 + 33) * 256]) : z2;
        float w00 = (1.f-fy)*(1.f-fx), w01 = (1.f-fy)*fx, w10 = fy*(1.f-fx), w11 = fy*fx;
        accx = fmaf(w, v00.x*w00 + v01.x*w01 + v10.x*w10 + v11.x*w11, accx);
        accy = fmaf(w, v00.y*w00 + v01.y*w01 + v10.y*w10 + v11.y*w11, accy);
    }
    ((__half2*)msh)[(size_t)bq * 256 + head * 32 + c2] = __floats2half2_rn(accx, accy);
}

// ---------------- residual + LN: src recomputed from fp16 pre + stats ----------------
__global__ void ln_res(const __half* __restrict__ pre, const float* __restrict__ stats,
                       const float* __restrict__ gv, const float* __restrict__ bev,
                       const float* __restrict__ gi, const float* __restrict__ bei,
                       const __half* __restrict__ att,
                       const float* __restrict__ g, const float* __restrict__ be,
                       __half* __restrict__ cath)
{
    int grow = blockIdx.x;            // b*2048 + lvl*1024 + hw
    size_t base = (size_t)grow * DD;
    int t = threadIdx.x;              // 256
    int bee = grow >> 10, lvl = bee & 1;
    const float* gam = lvl ? gi : gv;
    const float* bet = lvl ? bei : bev;
    float mean0 = stats[(bee * 32 + (t >> 4)) * 2];
    float rstd0 = stats[(bee * 32 + (t >> 4)) * 2 + 1];
    int t2 = t + 256;
    float mean1 = stats[(bee * 32 + (t2 >> 4)) * 2];
    float rstd1 = stats[(bee * 32 + (t2 >> 4)) * 2 + 1];
    float s0 = (__half2float(pre[base + t])  - mean0) * rstd0 * gam[t]  + bet[t];
    float s1 = (__half2float(pre[base + t2]) - mean1) * rstd1 * gam[t2] + bet[t2];
    float v0 = s0 + __half2float(att[base + t]);
    float v1 = s1 + __half2float(att[base + t2]);
    float s = v0 + v1, sq = v0*v0 + v1*v1;
    __shared__ float red[16];
    for (int o = 16; o > 0; o >>= 1) {
        s  += __shfl_down_sync(0xffffffffu, s,  o);
        sq += __shfl_down_sync(0xffffffffu, sq, o);
    }
    if ((t & 31) == 0) { red[t >> 5] = s; red[8 + (t >> 5)] = sq; }
    __syncthreads();
    if (t < 32) {
        s  = (t < 8) ? red[t]     : 0.f;
        sq = (t < 8) ? red[8 + t] : 0.f;
        for (int o = 4; o > 0; o >>= 1) {
            s  += __shfl_down_sync(0xffffffffu, s,  o);
            sq += __shfl_down_sync(0xffffffffu, sq, o);
        }
        if (t == 0) { red[0] = s; red[8] = sq; }
    }
    __syncthreads();
    float mu   = red[0] * (1.f/512.f);
    float var  = red[8] * (1.f/512.f) - mu * mu;
    float rstd = rsqrtf(var + 1e-5f);
    int b = grow >> 11, hw = grow & 1023;
    size_t obase = ((size_t)b * 1024 + hw) * 1024 + lvl * 512;
    cath[obase + t]       = __float2half_rn((v0 - mu) * rstd * g[t]  + be[t]);
    cath[obase + t + 256] = __float2half_rn((v1 - mu) * rstd * g[t2] + be[t2]);
}

// ---------------- GN stats: contiguous fp16 groups (conv2 output) ----------------
__global__ void gn_stats_h(const __half* __restrict__ x, float* __restrict__ stats, int groupElems)
{
    int idx = blockIdx.y * gridDim.x + blockIdx.x;
    const __half* p = x + (size_t)idx * groupElems;
    float s = 0.f, sq = 0.f;
    for (int i = threadIdx.x * 8; i < groupElems; i += blockDim.x * 8) {
        uint4 raw = *(const uint4*)(p + i);
        float2 a = __half22float2(*(__half2*)&raw.x);
        float2 b = __half22float2(*(__half2*)&raw.y);
        float2 c = __half22float2(*(__half2*)&raw.z);
        float2 d = __half22float2(*(__half2*)&raw.w);
        s  += a.x + a.y + b.x + b.y + c.x + c.y + d.x + d.y;
        sq += a.x*a.x + a.y*a.y + b.x*b.x + b.y*b.y + c.x*c.x + c.y*c.y + d.x*d.x + d.y*d.y;
    }
    __shared__ float red[16];
    int t = threadIdx.x;
    for (int o = 16; o > 0; o >>= 1) {
        s  += __shfl_down_sync(0xffffffffu, s,  o);
        sq += __shfl_down_sync(0xffffffffu, sq, o);
    }
    if ((t & 31) == 0) { red[t >> 5] = s; red[8 + (t >> 5)] = sq; }
    __syncthreads();
    if (t < 32) {
        s  = (t < 8) ? red[t]     : 0.f;
        sq = (t < 8) ? red[8 + t] : 0.f;
        for (int o = 4; o > 0; o >>= 1) {
            s  += __shfl_down_sync(0xffffffffu, s,  o);
            sq += __shfl_down_sync(0xffffffffu, sq, o);
        }
        if (t == 0) {
            float inv = 1.f / (float)groupElems;
            float mean = s * inv;
            stats[idx*2]   = mean;
            stats[idx*2+1] = rsqrtf(sq * inv - mean * mean + 1e-5f);
        }
    }
}

__global__ void gn2_finish(const __half* __restrict__ x, const float* __restrict__ stats,
    const float* __restrict__ gc, const float* __restrict__ bec, float* __restrict__ out)
{
    size_t i2 = ((size_t)blockIdx.x * blockDim.x + threadIdx.x) * 2;
    int hwch = (int)(i2 >> 10);
    int ch = hwch % 768;
    int b  = hwch / 768;
    int g  = ch / 24;
    float mean = stats[(b*32 + g) * 2];
    float rstd = stats[(b*32 + g) * 2 + 1];
    float2 v = __half22float2(*(const __half2*)(x + i2));
    float gg = gc[ch], bb = bec[ch];
    *(float2*)(out + i2) = make_float2((v.x - mean) * rstd * gg + bb,
                                       (v.y - mean) * rstd * gg + bb);
}

// ---------------- launcher ----------------
#define SYM(T, v, s) T v; cudaGetSymbolAddress((void**)&v, s)
extern "C" void kernel_launch(void* const* d_in, const int* in_sizes, int n_in,
                              void* d_out, int out_size)
{
    const float* input_v = (const float*)d_in[0];
    const float* input_i = (const float*)d_in[1];
    const float* wv      = (const float*)d_in[2];
    const float* bv      = (const float*)d_in[3];
    const float* gv      = (const float*)d_in[4];
    const float* bev     = (const float*)d_in[5];
    const float* wi      = (const float*)d_in[6];
    const float* bi      = (const float*)d_in[7];
    const float* gi      = (const float*)d_in[8];
    const float* bei     = (const float*)d_in[9];
    const float* le      = (const float*)d_in[10];
    const float* w_off   = (const float*)d_in[11];
    const float* b_off   = (const float*)d_in[12];
    const float* w_attn  = (const float*)d_in[13];
    const float* b_attn  = (const float*)d_in[14];
    const float* w_val   = (const float*)d_in[15];
    const float* b_val   = (const float*)d_in[16];
    const float* w_out   = (const float*)d_in[17];
    const float* b_out   = (const float*)d_in[18];
    const float* ln_g    = (const float*)d_in[19];
    const float* ln_b    = (const float*)d_in[20];
    const float* wc      = (const float*)d_in[21];
    const float* bc      = (const float*)d_in[22];
    const float* gc      = (const float*)d_in[23];
    const float* bec     = (const float*)d_in[24];

    SYM(__half*, xth,  g_xth);
    SYM(__half*, w1h,  g_w1h);  SYM(__half*, wvoa, g_wvoa);
    SYM(__half*, wouth,g_wouth);
    SYM(__half*, wch,  g_wch_);
    SYM(__half*, preh, g_preh);
    SYM(__half*, srch, g_srch);
    SYM(__half*, msh,  g_msh);
    SYM(__half*, cath, g_cath); SYM(__half*, vph,  g_vph);
    SYM(__half*, attno, g_attnoh);
    SYM(__half*, conv2h, g_conv2h);
    SYM(__half*, oah,  g_oah);
    SYM(float*, lep,   g_lep);    SYM(float*, b1,    g_b1);
    SYM(float*, st1,   g_stats1); SYM(float*, st2,   g_stats2);
    size_t XT = (size_t)8192*768;

    cudaFuncSetAttribute(gemm_tc, cudaFuncAttributeMaxDynamicSharedMemorySize, GEMM_SMEM);

    // unified prep (weights + leproj + input transposes), one launch
    prep_all<<<20998, 256>>>(wv, wi, w_val, w_out, w_off, w_attn, wc, bv, bi,
                             le, b_off, b_attn, input_v, input_i,
                             w1h, wvoa, wouth, wch, b1, lep, xth);

    // conv1 (v+i, z planes): fp16 D -> rows (b, lvl, hw)
    gemm_tc<<<dim3(4, 64, 2), 256, GEMM_SMEM>>>(xth, w1h, b1, preh,
        768, 2, 2048, 0, 512, (long)XT, 393216L, 512, 1024, 0, nullptr, nullptr);
    // GN1
    gn_stats_seq<<<dim3(32, 16), 256>>>(preh, st1);
    gn1_finish2<<<4096, 256>>>(preh, st1, gv, bev, gi, bei, srch);
    // fused vproj+oa projection [dual fp16 output]
    gemm_tc<<<dim3(6, 128), 256, GEMM_SMEM>>>(srch, wvoa, b_val, vph,
        512, 3, 1024, 0, 512, 0L, 0L, 0, 0, 0, oah, lep);
    // sampling (softmax fused, 2 queries per block)
    msda_sample<<<MROWS/2, 512>>>(vph, oah, msh);
    // output projection [fp16 out]
    gemm_tc<<<dim3(4, 128), 256, GEMM_SMEM>>>(msh, wouth, b_out, attno,
        512, 2, 1024, 0, 512, 0L, 0L, 0, 0, 0, nullptr, nullptr);
    // residual + LN (src recomputed from preh) -> cat fp16
    ln_res<<<MROWS, 256>>>(preh, st1, gv, bev, gi, bei, attno, ln_g, ln_b, cath);
    // conv2: fp16 D -> (b, o, hw)
    gemm_tc<<<dim3(64, 6), 256, GEMM_SMEM>>>(wch, cath, bc, conv2h,
        1024, 4, 0, 0, 768, 0L, 0L, 0, 0, 0, nullptr, nullptr);
    // final GN
    gn_stats_h<<<dim3(32, BB), 256>>>(conv2h, st2, 24 * HWW);
    gn2_finish<<<12288, 256>>>(conv2h, st2, gc, bec, (float*)d_out);
}